// round 1
// baseline (speedup 1.0000x reference)
#include <cuda_runtime.h>

// AnchorLoss: sum over masked pairs of 1 - exp(-||(e_i+a_i)-(e_j+a_j)||^2 / 10)
// B=8, N=2048, D=2. Dominant cost: streaming the 134MB int32 mask once.

#define BATCH   8
#define NPTS    2048
#define TI      16          // rows per block
#define THREADS 256
#define NWARPS  (THREADS/32)

__global__ __launch_bounds__(THREADS) void anchor_loss_kernel(
    const float* __restrict__ emb,
    const float* __restrict__ abscoords,
    const int*   __restrict__ mask,
    float*       __restrict__ out)
{
    __shared__ float2 c[NPTS];          // 16 KB: combined points for this batch
    __shared__ float  wsum[NWARPS];

    const int b  = blockIdx.x >> 7;             // / (NPTS/TI = 128)
    const int i0 = (blockIdx.x & 127) * TI;

    // Build c = embedding + abs_coords for batch b
    const float2* e2 = reinterpret_cast<const float2*>(emb)       + (size_t)b * NPTS;
    const float2* a2 = reinterpret_cast<const float2*>(abscoords) + (size_t)b * NPTS;
    for (int j = threadIdx.x; j < NPTS; j += THREADS) {
        float2 e = e2[j];
        float2 a = a2[j];
        c[j] = make_float2(e.x + a.x, e.y + a.y);
    }
    __syncthreads();

    const int warp = threadIdx.x >> 5;
    const int lane = threadIdx.x & 31;
    const float kscale = -0.14426950408889634f;   // -log2(e)/TEMPERATURE

    float eacc = 0.0f;   // sum of exp terms over masked pairs
    int   cnt  = 0;      // count of masked pairs

    #pragma unroll
    for (int rr = 0; rr < TI / NWARPS; rr++) {
        const int i = i0 + warp * (TI / NWARPS) + rr;
        const float2 ci = c[i];
        const int4* mrow = reinterpret_cast<const int4*>(
            mask + ((size_t)b * NPTS + i) * NPTS);

        #pragma unroll 4
        for (int jc = lane; jc < NPTS / 4; jc += 32) {
            int4 m = mrow[jc];                               // 4 mask values
            const float4* c4 = reinterpret_cast<const float4*>(c) + 2 * jc;
            float4 p0 = c4[0];                               // points j..j+1
            float4 p1 = c4[1];                               // points j+2..j+3

            float dx, dy, d2, ev;

            dx = ci.x - p0.x; dy = ci.y - p0.y;
            d2 = fmaf(dx, dx, dy * dy);
            asm("ex2.approx.ftz.f32 %0, %1;" : "=f"(ev) : "f"(d2 * kscale));
            if (m.x) { cnt++; eacc += ev; }

            dx = ci.x - p0.z; dy = ci.y - p0.w;
            d2 = fmaf(dx, dx, dy * dy);
            asm("ex2.approx.ftz.f32 %0, %1;" : "=f"(ev) : "f"(d2 * kscale));
            if (m.y) { cnt++; eacc += ev; }

            dx = ci.x - p1.x; dy = ci.y - p1.y;
            d2 = fmaf(dx, dx, dy * dy);
            asm("ex2.approx.ftz.f32 %0, %1;" : "=f"(ev) : "f"(d2 * kscale));
            if (m.z) { cnt++; eacc += ev; }

            dx = ci.x - p1.z; dy = ci.y - p1.w;
            d2 = fmaf(dx, dx, dy * dy);
            asm("ex2.approx.ftz.f32 %0, %1;" : "=f"(ev) : "f"(d2 * kscale));
            if (m.w) { cnt++; eacc += ev; }
        }
    }

    // masked sum of (1 - e) = cnt - eacc
    float tot = (float)cnt - eacc;

    // warp reduce
    #pragma unroll
    for (int off = 16; off; off >>= 1)
        tot += __shfl_xor_sync(0xffffffffu, tot, off);
    if (lane == 0) wsum[warp] = tot;
    __syncthreads();

    if (threadIdx.x == 0) {
        float s = 0.0f;
        #pragma unroll
        for (int w = 0; w < NWARPS; w++) s += wsum[w];
        atomicAdd(out, s);
    }
}

extern "C" void kernel_launch(void* const* d_in, const int* in_sizes, int n_in,
                              void* d_out, int out_size)
{
    const float* emb  = (const float*)d_in[0];
    const float* absc = (const float*)d_in[1];
    const int*   mask = (const int*)d_in[2];
    float*       out  = (float*)d_out;

    cudaMemsetAsync(out, 0, sizeof(float));

    dim3 grid(BATCH * (NPTS / TI));   // 1024 blocks
    anchor_loss_kernel<<<grid, THREADS>>>(emb, absc, mask, out);
}

// round 2
// speedup vs baseline: 1.0008x; 1.0008x over previous
#include <cuda_runtime.h>

// AnchorLoss: sum over masked pairs of 1 - exp(-||(e_i+a_i)-(e_j+a_j)||^2 / 10)
// B=8, N=2048, D=2. Dominant cost: streaming the 134MB int32 mask once (~17us floor).
//
// Strategy: block = 8 rows of one batch; points (pre-scaled by sqrt(log2(e)/10))
// staged in smem; each warp processes 2 adjacent rows sharing the same point
// loads (halves LDS, doubles independent LDG streams). exp(-d2/10) computed as
// ex2(-(s*dx)^2-(s*dy)^2) with free SASS source negation.

#define BATCH   8
#define NPTS    2048
#define TI      8           // rows per block
#define THREADS 128
#define NWARPS  (THREADS/32)

__global__ __launch_bounds__(THREADS) void anchor_loss_kernel(
    const float* __restrict__ emb,
    const float* __restrict__ abscoords,
    const int*   __restrict__ mask,
    float*       __restrict__ out)
{
    __shared__ __align__(16) float2 c[NPTS];   // 16 KB: scaled combined points
    __shared__ float wsum[NWARPS];

    const int b  = blockIdx.x >> 8;            // 256 blocks per batch
    const int i0 = (blockIdx.x & 255) * TI;

    // sqrt(log2(e)/TEMPERATURE): so dist2_scaled = (log2 e / 10) * dist2,
    // and exp(-dist2/10) = 2^(-dist2_scaled).
    const float S = 0.37982354f;   // sqrtf(0.14426950408889634f)

    const float2* e2 = reinterpret_cast<const float2*>(emb)       + (size_t)b * NPTS;
    const float2* a2 = reinterpret_cast<const float2*>(abscoords) + (size_t)b * NPTS;
    for (int j = threadIdx.x; j < NPTS; j += THREADS) {
        float2 e = e2[j];
        float2 a = a2[j];
        c[j] = make_float2((e.x + a.x) * S, (e.y + a.y) * S);
    }
    __syncthreads();

    const int warp = threadIdx.x >> 5;
    const int lane = threadIdx.x & 31;

    // Two adjacent rows per warp, sharing point loads.
    const int iA = i0 + warp * 2;
    const int iB = iA + 1;
    const float2 ciA = c[iA];
    const float2 ciB = c[iB];

    const int4* mrowA = reinterpret_cast<const int4*>(
        mask + ((size_t)b * NPTS + iA) * NPTS) + lane;
    const int4* mrowB = reinterpret_cast<const int4*>(
        mask + ((size_t)b * NPTS + iB) * NPTS) + lane;
    const float4* c4 = reinterpret_cast<const float4*>(c) + 2 * lane;

    float eA = 0.0f, eB = 0.0f;
    int   cA = 0,    cB = 0;

    #pragma unroll 4
    for (int u = 0; u < NPTS / 4 / 32; u++) {      // 16 iterations
        int4 ma = __ldcs(mrowA + 32 * u);          // masks row A: 4 pairs
        int4 mb = __ldcs(mrowB + 32 * u);          // masks row B: 4 pairs
        float4 p0 = c4[64 * u];                    // points j..j+1   (scaled)
        float4 p1 = c4[64 * u + 1];                // points j+2..j+3 (scaled)

        float dx, dy, d2n, ev;

        // ---- row A ----
        dx = ciA.x - p0.x; dy = ciA.y - p0.y;
        d2n = fmaf(dx, -dx, dy * -dy);
        asm("ex2.approx.ftz.f32 %0, %1;" : "=f"(ev) : "f"(d2n));
        if (ma.x) eA += ev;

        dx = ciA.x - p0.z; dy = ciA.y - p0.w;
        d2n = fmaf(dx, -dx, dy * -dy);
        asm("ex2.approx.ftz.f32 %0, %1;" : "=f"(ev) : "f"(d2n));
        if (ma.y) eA += ev;

        dx = ciA.x - p1.x; dy = ciA.y - p1.y;
        d2n = fmaf(dx, -dx, dy * -dy);
        asm("ex2.approx.ftz.f32 %0, %1;" : "=f"(ev) : "f"(d2n));
        if (ma.z) eA += ev;

        dx = ciA.x - p1.z; dy = ciA.y - p1.w;
        d2n = fmaf(dx, -dx, dy * -dy);
        asm("ex2.approx.ftz.f32 %0, %1;" : "=f"(ev) : "f"(d2n));
        if (ma.w) eA += ev;

        cA += ma.x + ma.y;         // mask values are 0/1: count by summing
        cA += ma.z + ma.w;

        // ---- row B (same points) ----
        dx = ciB.x - p0.x; dy = ciB.y - p0.y;
        d2n = fmaf(dx, -dx, dy * -dy);
        asm("ex2.approx.ftz.f32 %0, %1;" : "=f"(ev) : "f"(d2n));
        if (mb.x) eB += ev;

        dx = ciB.x - p0.z; dy = ciB.y - p0.w;
        d2n = fmaf(dx, -dx, dy * -dy);
        asm("ex2.approx.ftz.f32 %0, %1;" : "=f"(ev) : "f"(d2n));
        if (mb.y) eB += ev;

        dx = ciB.x - p1.x; dy = ciB.y - p1.y;
        d2n = fmaf(dx, -dx, dy * -dy);
        asm("ex2.approx.ftz.f32 %0, %1;" : "=f"(ev) : "f"(d2n));
        if (mb.z) eB += ev;

        dx = ciB.x - p1.z; dy = ciB.y - p1.w;
        d2n = fmaf(dx, -dx, dy * -dy);
        asm("ex2.approx.ftz.f32 %0, %1;" : "=f"(ev) : "f"(d2n));
        if (mb.w) eB += ev;

        cB += mb.x + mb.y;
        cB += mb.z + mb.w;
    }

    // masked sum of (1 - e) = cnt - eacc
    float tot = (float)(cA + cB) - (eA + eB);

    #pragma unroll
    for (int off = 16; off; off >>= 1)
        tot += __shfl_xor_sync(0xffffffffu, tot, off);
    if (lane == 0) wsum[warp] = tot;
    __syncthreads();

    if (threadIdx.x == 0) {
        float s = 0.0f;
        #pragma unroll
        for (int w = 0; w < NWARPS; w++) s += wsum[w];
        atomicAdd(out, s);
    }
}

extern "C" void kernel_launch(void* const* d_in, const int* in_sizes, int n_in,
                              void* d_out, int out_size)
{
    const float* emb  = (const float*)d_in[0];
    const float* absc = (const float*)d_in[1];
    const int*   mask = (const int*)d_in[2];
    float*       out  = (float*)d_out;

    cudaMemsetAsync(out, 0, sizeof(float));

    dim3 grid(BATCH * (NPTS / TI));   // 2048 blocks
    anchor_loss_kernel<<<grid, THREADS>>>(emb, absc, mask, out);
}

// round 3
// speedup vs baseline: 1.2515x; 1.2505x over previous
#include <cuda_runtime.h>

// AnchorLoss: sum over masked pairs of 1 - exp(-||(e_i+a_i)-(e_j+a_j)||^2 / 10)
// B=8, N=2048, D=2. Dominant cost: streaming the 134MB int32 mask once (~17us floor).
//
// R3 strategy: latency-bound fix. Each warp owns 4 adjacent rows = 4 independent
// mask LDG streams, double-buffered in registers so 4 loads are always in flight
// while ~100 instructions of compute retire. Points (pre-scaled by sqrt(log2e/10))
// staged once in smem and shared across all 4 rows.

#define BATCH   8
#define NPTS    2048
#define TI      16          // rows per block
#define THREADS 128
#define NWARPS  (THREADS/32)
#define ROWS_PW 4           // rows per warp
#define NITER   (NPTS/4/32) // 16 int4-chunks per lane per row

__global__ __launch_bounds__(THREADS) void anchor_loss_kernel(
    const float* __restrict__ emb,
    const float* __restrict__ abscoords,
    const int*   __restrict__ mask,
    float*       __restrict__ out)
{
    __shared__ __align__(16) float2 c[NPTS];   // 16 KB: scaled combined points
    __shared__ float wsum[NWARPS];

    const int b  = blockIdx.x >> 7;            // 128 blocks per batch
    const int i0 = (blockIdx.x & 127) * TI;

    // sqrt(log2(e)/TEMPERATURE): exp(-d2/10) = 2^(-(S*dx)^2-(S*dy)^2)
    const float S = 0.37982354f;

    const float2* e2 = reinterpret_cast<const float2*>(emb)       + (size_t)b * NPTS;
    const float2* a2 = reinterpret_cast<const float2*>(abscoords) + (size_t)b * NPTS;
    for (int j = threadIdx.x; j < NPTS; j += THREADS) {
        float2 e = e2[j];
        float2 a = a2[j];
        c[j] = make_float2((e.x + a.x) * S, (e.y + a.y) * S);
    }
    __syncthreads();

    const int warp = threadIdx.x >> 5;
    const int lane = threadIdx.x & 31;

    const int iA = i0 + warp * ROWS_PW;        // first of 4 adjacent rows

    float2 ci[ROWS_PW];
    #pragma unroll
    for (int r = 0; r < ROWS_PW; r++) ci[r] = c[iA + r];

    // One base pointer; rows are immediate offsets of 512 int4 (8KB) each.
    const int4* mbase = reinterpret_cast<const int4*>(
        mask + ((size_t)b * NPTS + iA) * NPTS) + lane;
    const float4* c4 = reinterpret_cast<const float4*>(c) + 2 * lane;

    float eacc[ROWS_PW] = {0.f, 0.f, 0.f, 0.f};
    int   cnt [ROWS_PW] = {0, 0, 0, 0};

    // prologue: load chunk 0 for all 4 rows
    int4 mc[ROWS_PW];
    #pragma unroll
    for (int r = 0; r < ROWS_PW; r++) mc[r] = __ldcs(mbase + 512 * r);

    #pragma unroll 2
    for (int u = 0; u < NITER; u++) {
        // prefetch next chunk for all 4 rows (wraps to chunk 0 on last iter:
        // always in-bounds, result discarded)
        int4 mn[ROWS_PW];
        const int un = (u + 1) & (NITER - 1);
        #pragma unroll
        for (int r = 0; r < ROWS_PW; r++)
            mn[r] = __ldcs(mbase + 512 * r + 32 * un);

        float4 p0 = c4[64 * u];                // points 4u..4u+1 (scaled)
        float4 p1 = c4[64 * u + 1];            // points 4u+2..4u+3

        #pragma unroll
        for (int r = 0; r < ROWS_PW; r++) {
            const float cx = ci[r].x, cy = ci[r].y;
            const int4  m  = mc[r];
            float dx, dy, d2n, ev;

            dx = cx - p0.x; dy = cy - p0.y;
            d2n = fmaf(dx, -dx, dy * -dy);
            asm("ex2.approx.ftz.f32 %0, %1;" : "=f"(ev) : "f"(d2n));
            if (m.x) eacc[r] += ev;

            dx = cx - p0.z; dy = cy - p0.w;
            d2n = fmaf(dx, -dx, dy * -dy);
            asm("ex2.approx.ftz.f32 %0, %1;" : "=f"(ev) : "f"(d2n));
            if (m.y) eacc[r] += ev;

            dx = cx - p1.x; dy = cy - p1.y;
            d2n = fmaf(dx, -dx, dy * -dy);
            asm("ex2.approx.ftz.f32 %0, %1;" : "=f"(ev) : "f"(d2n));
            if (m.z) eacc[r] += ev;

            dx = cx - p1.z; dy = cy - p1.w;
            d2n = fmaf(dx, -dx, dy * -dy);
            asm("ex2.approx.ftz.f32 %0, %1;" : "=f"(ev) : "f"(d2n));
            if (m.w) eacc[r] += ev;

            cnt[r] += (m.x + m.y) + (m.z + m.w);   // mask values are 0/1
        }

        #pragma unroll
        for (int r = 0; r < ROWS_PW; r++) mc[r] = mn[r];
    }

    // masked sum of (1 - e) = cnt - eacc
    float tot = 0.0f;
    #pragma unroll
    for (int r = 0; r < ROWS_PW; r++)
        tot += (float)cnt[r] - eacc[r];

    #pragma unroll
    for (int off = 16; off; off >>= 1)
        tot += __shfl_xor_sync(0xffffffffu, tot, off);
    if (lane == 0) wsum[warp] = tot;
    __syncthreads();

    if (threadIdx.x == 0) {
        float s = 0.0f;
        #pragma unroll
        for (int w = 0; w < NWARPS; w++) s += wsum[w];
        atomicAdd(out, s);
    }
}

extern "C" void kernel_launch(void* const* d_in, const int* in_sizes, int n_in,
                              void* d_out, int out_size)
{
    const float* emb  = (const float*)d_in[0];
    const float* absc = (const float*)d_in[1];
    const int*   mask = (const int*)d_in[2];
    float*       out  = (float*)d_out;

    cudaMemsetAsync(out, 0, sizeof(float));

    dim3 grid(BATCH * (NPTS / TI));   // 1024 blocks
    anchor_loss_kernel<<<grid, THREADS>>>(emb, absc, mask, out);
}